// round 2
// baseline (speedup 1.0000x reference)
#include <cuda_runtime.h>
#include <math.h>

#define N_V    100000
#define NE_    20000
#define NNZ_   1600000
#define NFEAT_ 128
#define NHID_  64
#define NCLASS_ 40
#define NLAYER_ 4

// ---------------- device scratch (static, no allocation) ----------------
__device__ float g_X [N_V * NHID_];   // current features
__device__ float g_X0[N_V * NHID_];   // residual anchor
__device__ float g_Xe[NE_ * NHID_];   // edge features (pre-scaled by degE/count)
__device__ float g_escale[NE_];
__device__ int   g_cntE[NE_];
__device__ int   g_cntV[N_V];
__device__ int   g_lenE[NE_];
__device__ int   g_lenV[N_V];
__device__ int   g_offE[NE_];
__device__ int   g_offV[N_V];
__device__ int   g_curE;
__device__ int   g_curV;
__device__ int   g_adjE[NNZ_];        // members (vertex ids) per edge
__device__ int   g_adjV[NNZ_];        // incident edges per vertex

// ---------------- CSR build ----------------
__global__ void zero_cnt_k() {
    int i = blockIdx.x * blockDim.x + threadIdx.x;
    if (i < NE_) g_cntE[i] = 0;
    if (i < N_V) g_cntV[i] = 0;
    if (i == 0) { g_curE = 0; g_curV = 0; }
}

__global__ void hist_k(const int* __restrict__ vertex, const int* __restrict__ edges) {
    int i = blockIdx.x * blockDim.x + threadIdx.x;
    if (i < NNZ_) {
        atomicAdd(&g_cntE[edges[i]], 1);
        atomicAdd(&g_cntV[vertex[i]], 1);
    }
}

// warp-aggregated bump allocation of CSR offsets (order across segments is
// arbitrary but valid; per-segment sums are order-independent).
// i in [0, NE_) -> edges,  i in [NE_, NE_+N_V) -> vertices.
// Also: escale = degE/max(cnt,1); len = cnt; cnt reset to 0 for build phase.
__global__ void alloc_k(const float* __restrict__ degE) {
    int i = blockIdx.x * blockDim.x + threadIdx.x;
    const int n = NE_ + N_V;
    // NE_ and n are multiples of 32 -> warps never straddle / go partially OOB
    if (i >= n) return;
    int lane = threadIdx.x & 31;
    bool isE = (i < NE_);
    int c = isE ? g_cntE[i] : g_cntV[i - NE_];
    int inc = c;
    #pragma unroll
    for (int o = 1; o < 32; o <<= 1) {
        int t = __shfl_up_sync(0xffffffffu, inc, o);
        if (lane >= o) inc += t;
    }
    int base = 0;
    if (lane == 31)
        base = atomicAdd(isE ? &g_curE : &g_curV, inc);
    base = __shfl_sync(0xffffffffu, base, 31);
    int off = base + inc - c;
    if (isE) {
        g_offE[i] = off;
        g_lenE[i] = c;
        g_escale[i] = degE[i] / fmaxf((float)c, 1.0f);
        g_cntE[i] = 0;
    } else {
        g_offV[i - NE_] = off;
        g_lenV[i - NE_] = c;
        g_cntV[i - NE_] = 0;
    }
}

__global__ void build_adj_k(const int* __restrict__ vertex, const int* __restrict__ edges) {
    int i = blockIdx.x * blockDim.x + threadIdx.x;
    if (i < NNZ_) {
        int v = vertex[i], e = edges[i];
        int pe = g_offE[e] + atomicAdd(&g_cntE[e], 1);
        g_adjE[pe] = v;
        int pv = g_offV[v] + atomicAdd(&g_cntV[v], 1);
        g_adjV[pv] = e;
    }
}

// ---------------- vertex -> edge mean (warp per edge, float2 lanes) ----------------
__global__ void __launch_bounds__(256) agg_ve_k() {
    int e = blockIdx.x * 8 + (threadIdx.x >> 5);
    if (e >= NE_) return;
    int lane = threadIdx.x & 31;
    int beg = g_offE[e], len = g_lenE[e];
    float ax = 0.f, ay = 0.f;
    const float* __restrict__ X = g_X;
    int j = 0;
    for (; j + 8 <= len; j += 8) {
        int i0 = g_adjE[beg + j + 0], i1 = g_adjE[beg + j + 1];
        int i2 = g_adjE[beg + j + 2], i3 = g_adjE[beg + j + 3];
        int i4 = g_adjE[beg + j + 4], i5 = g_adjE[beg + j + 5];
        int i6 = g_adjE[beg + j + 6], i7 = g_adjE[beg + j + 7];
        float2 t0 = __ldg((const float2*)&X[i0 * NHID_ + lane * 2]);
        float2 t1 = __ldg((const float2*)&X[i1 * NHID_ + lane * 2]);
        float2 t2 = __ldg((const float2*)&X[i2 * NHID_ + lane * 2]);
        float2 t3 = __ldg((const float2*)&X[i3 * NHID_ + lane * 2]);
        float2 t4 = __ldg((const float2*)&X[i4 * NHID_ + lane * 2]);
        float2 t5 = __ldg((const float2*)&X[i5 * NHID_ + lane * 2]);
        float2 t6 = __ldg((const float2*)&X[i6 * NHID_ + lane * 2]);
        float2 t7 = __ldg((const float2*)&X[i7 * NHID_ + lane * 2]);
        ax += t0.x + t1.x + t2.x + t3.x + t4.x + t5.x + t6.x + t7.x;
        ay += t0.y + t1.y + t2.y + t3.y + t4.y + t5.y + t6.y + t7.y;
    }
    for (; j < len; j++) {
        int v = g_adjE[beg + j];
        float2 t = __ldg((const float2*)&X[v * NHID_ + lane * 2]);
        ax += t.x; ay += t.y;
    }
    float s = g_escale[e];
    float2 r; r.x = ax * s; r.y = ay * s;
    *(float2*)&g_Xe[e * NHID_ + lane * 2] = r;
}

// ---------------- fused: edge->vertex sum, *degV, L2 norm, alpha-mix,
//                  Xi@W GEMM (W in registers), beta-mix, relu ----------------
// 64-thread group per vertex (2 warps), 4 groups per 256-thread block,
// persistent grid. Named barriers per group.
__device__ __forceinline__ void barg(int id) {
    asm volatile("bar.sync %0, 64;" :: "r"(id) : "memory");
}

__global__ void __launch_bounds__(256, 2) agg_ev_gemm_k(
    const float* __restrict__ degV, const float* __restrict__ W,
    float c0, float c1)
{
    int g    = threadIdx.x >> 6;        // group 0..3
    int f    = threadIdx.x & 63;        // feature
    int lane = threadIdx.x & 31;
    int wh   = (threadIdx.x >> 5) & 1;  // warp-in-group

    __shared__ __align__(16) float srow[4][64];
    __shared__ float sss[4][2];

    // W column f -> registers (fully unrolled so it stays in regs)
    float Wreg[64];
    #pragma unroll
    for (int k = 0; k < 64; k++) Wreg[k] = __ldg(&W[k * 64 + f]);

    const int unit   = blockIdx.x * 4 + g;
    const int stride = gridDim.x * 4;
    const float* __restrict__ Xe = g_Xe;

    for (int v = unit; v < N_V; v += stride) {
        int beg = g_offV[v], len = g_lenV[v];
        float acc = 0.f;
        int j = 0;
        for (; j + 8 <= len; j += 8) {
            int e0 = g_adjV[beg + j + 0], e1 = g_adjV[beg + j + 1];
            int e2 = g_adjV[beg + j + 2], e3 = g_adjV[beg + j + 3];
            int e4 = g_adjV[beg + j + 4], e5 = g_adjV[beg + j + 5];
            int e6 = g_adjV[beg + j + 6], e7 = g_adjV[beg + j + 7];
            float t0 = __ldg(&Xe[e0 * NHID_ + f]);
            float t1 = __ldg(&Xe[e1 * NHID_ + f]);
            float t2 = __ldg(&Xe[e2 * NHID_ + f]);
            float t3 = __ldg(&Xe[e3 * NHID_ + f]);
            float t4 = __ldg(&Xe[e4 * NHID_ + f]);
            float t5 = __ldg(&Xe[e5 * NHID_ + f]);
            float t6 = __ldg(&Xe[e6 * NHID_ + f]);
            float t7 = __ldg(&Xe[e7 * NHID_ + f]);
            acc += ((t0 + t1) + (t2 + t3)) + ((t4 + t5) + (t6 + t7));
        }
        for (; j < len; j++) {
            int e = g_adjV[beg + j];
            acc += __ldg(&Xe[e * NHID_ + f]);
        }
        acc *= __ldg(&degV[v]);

        // cross-warp L2 norm of the 64-wide row
        float ss = acc * acc;
        #pragma unroll
        for (int o = 16; o; o >>= 1) ss += __shfl_xor_sync(0xffffffffu, ss, o);
        if (lane == 0) sss[g][wh] = ss;
        barg(g);
        float tot = sss[g][0] + sss[g][1];
        float scale = (tot > 0.f) ? rsqrtf(tot) : 0.f;
        float xi = 0.9f * acc * scale + 0.1f * g_X0[(size_t)v * NHID_ + f];
        srow[g][f] = xi;
        barg(g);

        // dot(xi_row, W[:,f]) — float4 smem broadcast + register W
        const float4* r4 = (const float4*)srow[g];
        float dot = 0.f;
        #pragma unroll
        for (int k4 = 0; k4 < 16; k4++) {
            float4 x = r4[k4];
            dot += x.x * Wreg[4 * k4 + 0] + x.y * Wreg[4 * k4 + 1]
                 + x.z * Wreg[4 * k4 + 2] + x.w * Wreg[4 * k4 + 3];
        }
        g_X[(size_t)v * NHID_ + f] = fmaxf(c0 * xi + c1 * dot, 0.f);
        // no third barrier needed: next iteration's srow/sss writes are
        // separated from this iteration's reads by barg(g) ordering.
    }
}

// ---------------- tiled GEMM (64 rows x NCOL), K chunked by 64 ----------------
// MODE 0: X = relu(A@W + b), also copy to X0.  (A = external x, K=128, NCOL=64)
// MODE 2: out = log_softmax(g_X@W + b).        (K=64, NCOL=40)
template <int K, int NCOL, int MODE>
__global__ void __launch_bounds__(256) gemm_k(
    const float* __restrict__ Aext, const float* __restrict__ W,
    const float* __restrict__ bias, float* __restrict__ outext)
{
    constexpr int KC = 64;
    constexpr int KP = KC + 4;
    constexpr int NP = (NCOL + 7) & ~3;
    __shared__ float As[64 * KP];
    __shared__ float Wsm[KC * NP];
    __shared__ float Ls[(MODE == 2) ? 64 * NCOL : 1];

    const float* A = (MODE == 0) ? Aext : g_X;
    const int M = N_V;
    int tid = threadIdx.x;
    int row0 = blockIdx.x * 64;
    int tx = tid & 15, ty = tid >> 4;
    bool active = (NCOL == 64) || (tx * 4 < NCOL);

    float acc[4][4] = {};

    for (int kc = 0; kc < K; kc += KC) {
        for (int idx = tid; idx < KC * NCOL; idx += 256) {
            int k = idx / NCOL, c = idx - k * NCOL;
            Wsm[k * NP + c] = W[(kc + k) * NCOL + c];
        }
        for (int idx = tid; idx < 64 * KC; idx += 256) {
            int r = idx >> 6, k = idx & 63;
            int row = row0 + r;
            As[r * KP + k] = (row < M) ? A[(size_t)row * K + kc + k] : 0.f;
        }
        __syncthreads();
        if (active) {
            #pragma unroll 8
            for (int k = 0; k < KC; k++) {
                float4 w = *(const float4*)&Wsm[k * NP + tx * 4];
                float a0 = As[(ty * 4 + 0) * KP + k];
                float a1 = As[(ty * 4 + 1) * KP + k];
                float a2 = As[(ty * 4 + 2) * KP + k];
                float a3 = As[(ty * 4 + 3) * KP + k];
                acc[0][0] += a0 * w.x; acc[0][1] += a0 * w.y; acc[0][2] += a0 * w.z; acc[0][3] += a0 * w.w;
                acc[1][0] += a1 * w.x; acc[1][1] += a1 * w.y; acc[1][2] += a1 * w.z; acc[1][3] += a1 * w.w;
                acc[2][0] += a2 * w.x; acc[2][1] += a2 * w.y; acc[2][2] += a2 * w.z; acc[2][3] += a2 * w.w;
                acc[3][0] += a3 * w.x; acc[3][1] += a3 * w.y; acc[3][2] += a3 * w.z; acc[3][3] += a3 * w.w;
            }
        }
        __syncthreads();
    }

    if (MODE == 0) {
        float bx = __ldg(bias + tx * 4 + 0), by = __ldg(bias + tx * 4 + 1);
        float bz = __ldg(bias + tx * 4 + 2), bw = __ldg(bias + tx * 4 + 3);
        #pragma unroll
        for (int i = 0; i < 4; i++) {
            int row = row0 + ty * 4 + i;
            if (row < M) {
                float4 r4;
                r4.x = fmaxf(acc[i][0] + bx, 0.f);
                r4.y = fmaxf(acc[i][1] + by, 0.f);
                r4.z = fmaxf(acc[i][2] + bz, 0.f);
                r4.w = fmaxf(acc[i][3] + bw, 0.f);
                *(float4*)&g_X [(size_t)row * NHID_ + tx * 4] = r4;
                *(float4*)&g_X0[(size_t)row * NHID_ + tx * 4] = r4;
            }
        }
    } else {  // MODE 2: logits + fused log_softmax
        if (active) {
            #pragma unroll
            for (int i = 0; i < 4; i++) {
                int r = ty * 4 + i;
                #pragma unroll
                for (int j = 0; j < 4; j++)
                    Ls[r * NCOL + tx * 4 + j] = acc[i][j] + __ldg(bias + tx * 4 + j);
            }
        }
        __syncthreads();
        if (tid < 64) {
            int row = row0 + tid;
            if (row < M) {
                float mx = -1e30f;
                #pragma unroll
                for (int c = 0; c < NCOL; c++) mx = fmaxf(mx, Ls[tid * NCOL + c]);
                float s = 0.f;
                #pragma unroll
                for (int c = 0; c < NCOL; c++) s += __expf(Ls[tid * NCOL + c] - mx);
                float lse = mx + __logf(s);
                #pragma unroll
                for (int c = 0; c < NCOL; c++)
                    outext[(size_t)row * NCOL + c] = Ls[tid * NCOL + c] - lse;
            }
        }
    }
}

// ---------------- launch ----------------
extern "C" void kernel_launch(void* const* d_in, const int* in_sizes, int n_in,
                              void* d_out, int out_size)
{
    const float* x    = (const float*)d_in[0];
    const float* degE = (const float*)d_in[1];
    const float* degV = (const float*)d_in[2];
    const float* W0   = (const float*)d_in[3];
    const float* b0   = (const float*)d_in[4];
    const float* Ws   = (const float*)d_in[5];
    const float* Wout = (const float*)d_in[6];
    const float* bout = (const float*)d_in[7];
    const int* vertex = (const int*)d_in[8];
    const int* edges  = (const int*)d_in[9];
    float* out = (float*)d_out;

    (void)in_sizes; (void)n_in; (void)out_size;

    const int GB = (N_V + 63) / 64;

    // CSR/CSC build (bump allocation, no serial scans)
    zero_cnt_k<<<(N_V + 255) / 256, 256>>>();
    hist_k<<<(NNZ_ + 255) / 256, 256>>>(vertex, edges);
    alloc_k<<<(NE_ + N_V + 255) / 256, 256>>>(degE);
    build_adj_k<<<(NNZ_ + 255) / 256, 256>>>(vertex, edges);

    // X = relu(x @ W0 + b0); X0 = X
    gemm_k<128, 64, 0><<<GB, 256>>>(x, W0, b0, nullptr);

    for (int i = 0; i < NLAYER_; i++) {
        float beta = logf(0.5f / (float)(i + 1) + 1.0f);
        agg_ve_k<<<(NE_ + 7) / 8, 256>>>();
        agg_ev_gemm_k<<<296, 256>>>(degV, Ws + (size_t)i * NHID_ * NHID_,
                                    1.0f - beta, beta);
    }

    // log_softmax(X @ Wout + bout)
    gemm_k<64, 40, 2><<<GB, 256>>>(nullptr, Wout, bout, out);
}

// round 3
// speedup vs baseline: 1.5482x; 1.5482x over previous
#include <cuda_runtime.h>
#include <math.h>

#define N_V    100000
#define NE_    20000
#define NNZ_   1600000
#define NFEAT_ 128
#define NHID_  64
#define NCLASS_ 40
#define NLAYER_ 4

// ---------------- device scratch (static, no allocation) ----------------
__device__ float g_X [N_V * NHID_];   // current features
__device__ float g_X0[N_V * NHID_];   // residual anchor
__device__ float g_Xe[NE_ * NHID_];   // edge features (pre-scaled by degE/count)
__device__ float g_escale[NE_];
__device__ int   g_cntE[NE_];
__device__ int   g_cntV[N_V];
__device__ int   g_lenE[NE_];
__device__ int   g_lenV[N_V];
__device__ int   g_offE[NE_];
__device__ int   g_offV[N_V];
__device__ int   g_curE;
__device__ int   g_curV;
__device__ int   g_adjE[NNZ_];        // members (vertex ids) per edge
__device__ int   g_adjV[NNZ_];        // incident edges per vertex

// ---------------- CSR build ----------------
__global__ void zero_cnt_k() {
    int i = blockIdx.x * blockDim.x + threadIdx.x;
    if (i < NE_) g_cntE[i] = 0;
    if (i < N_V) g_cntV[i] = 0;
    if (i == 0) { g_curE = 0; g_curV = 0; }
}

// 4 pairs per thread for MLP on the atomic chains
__global__ void hist_k(const int4* __restrict__ vertex4, const int4* __restrict__ edges4) {
    int i = blockIdx.x * blockDim.x + threadIdx.x;
    if (i < NNZ_ / 4) {
        int4 e = edges4[i];
        int4 v = vertex4[i];
        atomicAdd(&g_cntE[e.x], 1);
        atomicAdd(&g_cntE[e.y], 1);
        atomicAdd(&g_cntE[e.z], 1);
        atomicAdd(&g_cntE[e.w], 1);
        atomicAdd(&g_cntV[v.x], 1);
        atomicAdd(&g_cntV[v.y], 1);
        atomicAdd(&g_cntV[v.z], 1);
        atomicAdd(&g_cntV[v.w], 1);
    }
}

// warp-aggregated bump allocation of CSR offsets (segment order arbitrary but
// valid; per-segment sums are order-independent).
// i in [0, NE_) -> edges,  i in [NE_, NE_+N_V) -> vertices.
// Also: escale = degE/max(cnt,1); len = cnt; cnt reset to 0 for build phase.
__global__ void alloc_k(const float* __restrict__ degE) {
    int i = blockIdx.x * blockDim.x + threadIdx.x;
    const int n = NE_ + N_V;
    if (i >= n) return;           // NE_ and n are multiples of 32
    int lane = threadIdx.x & 31;
    bool isE = (i < NE_);
    int c = isE ? g_cntE[i] : g_cntV[i - NE_];
    int inc = c;
    #pragma unroll
    for (int o = 1; o < 32; o <<= 1) {
        int t = __shfl_up_sync(0xffffffffu, inc, o);
        if (lane >= o) inc += t;
    }
    int base = 0;
    if (lane == 31)
        base = atomicAdd(isE ? &g_curE : &g_curV, inc);
    base = __shfl_sync(0xffffffffu, base, 31);
    int off = base + inc - c;
    if (isE) {
        g_offE[i] = off;
        g_lenE[i] = c;
        g_escale[i] = degE[i] / fmaxf((float)c, 1.0f);
        g_cntE[i] = 0;
    } else {
        g_offV[i - NE_] = off;
        g_lenV[i - NE_] = c;
        g_cntV[i - NE_] = 0;
    }
}

__global__ void build_adj_k(const int4* __restrict__ vertex4, const int4* __restrict__ edges4) {
    int i = blockIdx.x * blockDim.x + threadIdx.x;
    if (i < NNZ_ / 4) {
        int4 v = vertex4[i];
        int4 e = edges4[i];
        int oe0 = g_offE[e.x], oe1 = g_offE[e.y], oe2 = g_offE[e.z], oe3 = g_offE[e.w];
        int ov0 = g_offV[v.x], ov1 = g_offV[v.y], ov2 = g_offV[v.z], ov3 = g_offV[v.w];
        int pe0 = oe0 + atomicAdd(&g_cntE[e.x], 1);
        int pe1 = oe1 + atomicAdd(&g_cntE[e.y], 1);
        int pe2 = oe2 + atomicAdd(&g_cntE[e.z], 1);
        int pe3 = oe3 + atomicAdd(&g_cntE[e.w], 1);
        int pv0 = ov0 + atomicAdd(&g_cntV[v.x], 1);
        int pv1 = ov1 + atomicAdd(&g_cntV[v.y], 1);
        int pv2 = ov2 + atomicAdd(&g_cntV[v.z], 1);
        int pv3 = ov3 + atomicAdd(&g_cntV[v.w], 1);
        g_adjE[pe0] = v.x; g_adjE[pe1] = v.y; g_adjE[pe2] = v.z; g_adjE[pe3] = v.w;
        g_adjV[pv0] = e.x; g_adjV[pv1] = e.y; g_adjV[pv2] = e.z; g_adjV[pv3] = e.w;
    }
}

// ---------------- vertex -> edge mean (warp per edge, float2 lanes) ----------------
__global__ void __launch_bounds__(256) agg_ve_k() {
    int e = blockIdx.x * 8 + (threadIdx.x >> 5);
    if (e >= NE_) return;
    int lane = threadIdx.x & 31;
    int beg = g_offE[e], len = g_lenE[e];
    float ax = 0.f, ay = 0.f;
    const float* __restrict__ X = g_X;
    int j = 0;
    for (; j + 8 <= len; j += 8) {
        int i0 = g_adjE[beg + j + 0], i1 = g_adjE[beg + j + 1];
        int i2 = g_adjE[beg + j + 2], i3 = g_adjE[beg + j + 3];
        int i4 = g_adjE[beg + j + 4], i5 = g_adjE[beg + j + 5];
        int i6 = g_adjE[beg + j + 6], i7 = g_adjE[beg + j + 7];
        float2 t0 = __ldg((const float2*)&X[i0 * NHID_ + lane * 2]);
        float2 t1 = __ldg((const float2*)&X[i1 * NHID_ + lane * 2]);
        float2 t2 = __ldg((const float2*)&X[i2 * NHID_ + lane * 2]);
        float2 t3 = __ldg((const float2*)&X[i3 * NHID_ + lane * 2]);
        float2 t4 = __ldg((const float2*)&X[i4 * NHID_ + lane * 2]);
        float2 t5 = __ldg((const float2*)&X[i5 * NHID_ + lane * 2]);
        float2 t6 = __ldg((const float2*)&X[i6 * NHID_ + lane * 2]);
        float2 t7 = __ldg((const float2*)&X[i7 * NHID_ + lane * 2]);
        ax += ((t0.x + t1.x) + (t2.x + t3.x)) + ((t4.x + t5.x) + (t6.x + t7.x));
        ay += ((t0.y + t1.y) + (t2.y + t3.y)) + ((t4.y + t5.y) + (t6.y + t7.y));
    }
    for (; j < len; j++) {
        int v = g_adjE[beg + j];
        float2 t = __ldg((const float2*)&X[v * NHID_ + lane * 2]);
        ax += t.x; ay += t.y;
    }
    float s = g_escale[e];
    float2 r; r.x = ax * s; r.y = ay * s;
    *(float2*)&g_Xe[e * NHID_ + lane * 2] = r;
}

// ---------------- edge -> vertex sum (warp per vertex, float2 lanes),
//                  fused *degV, L2 norm (shuffle-only), alpha-mix ----------------
__global__ void __launch_bounds__(256) agg_ev_k(const float* __restrict__ degV) {
    int v = blockIdx.x * 8 + (threadIdx.x >> 5);
    if (v >= N_V) return;
    int lane = threadIdx.x & 31;
    int beg = g_offV[v], len = g_lenV[v];
    float ax = 0.f, ay = 0.f;
    const float* __restrict__ Xe = g_Xe;
    int j = 0;
    for (; j + 8 <= len; j += 8) {
        int e0 = g_adjV[beg + j + 0], e1 = g_adjV[beg + j + 1];
        int e2 = g_adjV[beg + j + 2], e3 = g_adjV[beg + j + 3];
        int e4 = g_adjV[beg + j + 4], e5 = g_adjV[beg + j + 5];
        int e6 = g_adjV[beg + j + 6], e7 = g_adjV[beg + j + 7];
        float2 t0 = __ldg((const float2*)&Xe[e0 * NHID_ + lane * 2]);
        float2 t1 = __ldg((const float2*)&Xe[e1 * NHID_ + lane * 2]);
        float2 t2 = __ldg((const float2*)&Xe[e2 * NHID_ + lane * 2]);
        float2 t3 = __ldg((const float2*)&Xe[e3 * NHID_ + lane * 2]);
        float2 t4 = __ldg((const float2*)&Xe[e4 * NHID_ + lane * 2]);
        float2 t5 = __ldg((const float2*)&Xe[e5 * NHID_ + lane * 2]);
        float2 t6 = __ldg((const float2*)&Xe[e6 * NHID_ + lane * 2]);
        float2 t7 = __ldg((const float2*)&Xe[e7 * NHID_ + lane * 2]);
        ax += ((t0.x + t1.x) + (t2.x + t3.x)) + ((t4.x + t5.x) + (t6.x + t7.x));
        ay += ((t0.y + t1.y) + (t2.y + t3.y)) + ((t4.y + t5.y) + (t6.y + t7.y));
    }
    for (; j < len; j++) {
        int e = g_adjV[beg + j];
        float2 t = __ldg((const float2*)&Xe[e * NHID_ + lane * 2]);
        ax += t.x; ay += t.y;
    }
    float dv = __ldg(&degV[v]);
    ax *= dv; ay *= dv;
    // full row is in this warp -> shuffle-only L2 norm
    float ss = ax * ax + ay * ay;
    #pragma unroll
    for (int o = 16; o; o >>= 1) ss += __shfl_xor_sync(0xffffffffu, ss, o);
    float scale = (ss > 0.f) ? rsqrtf(ss) : 0.f;
    float2 x0 = *(const float2*)&g_X0[(size_t)v * NHID_ + lane * 2];
    float2 r;
    r.x = 0.9f * ax * scale + 0.1f * x0.x;
    r.y = 0.9f * ay * scale + 0.1f * x0.y;
    *(float2*)&g_X[(size_t)v * NHID_ + lane * 2] = r;
}

// ---------------- tiled GEMM (64 rows x NCOL), K chunked by 64 ----------------
// MODE 0: X = relu(A@W + b), also copy to X0.   (A = external x, K=128, NCOL=64)
// MODE 1: X = relu(c0*Xi + c1*(Xi@W)), in-place. (K=NCOL=64)
// MODE 2: out = log_softmax(g_X@W + b).          (K=64, NCOL=40)
template <int K, int NCOL, int MODE>
__global__ void __launch_bounds__(256) gemm_k(
    const float* __restrict__ Aext, const float* __restrict__ W,
    const float* __restrict__ bias, float* __restrict__ outext,
    float c0, float c1)
{
    constexpr int KC = 64;
    constexpr int KP = KC + 4;
    constexpr int NP = (NCOL + 7) & ~3;
    __shared__ float As[64 * KP];
    __shared__ float Wsm[KC * NP];
    __shared__ float Ls[(MODE == 2) ? 64 * NCOL : 1];

    const float* A = (MODE == 0) ? Aext : g_X;
    const int M = N_V;
    int tid = threadIdx.x;
    int row0 = blockIdx.x * 64;
    int tx = tid & 15, ty = tid >> 4;
    bool active = (NCOL == 64) || (tx * 4 < NCOL);

    float acc[4][4] = {};

    for (int kc = 0; kc < K; kc += KC) {
        for (int idx = tid; idx < KC * NCOL; idx += 256) {
            int k = idx / NCOL, c = idx - k * NCOL;
            Wsm[k * NP + c] = W[(kc + k) * NCOL + c];
        }
        for (int idx = tid; idx < 64 * KC; idx += 256) {
            int r = idx >> 6, k = idx & 63;
            int row = row0 + r;
            As[r * KP + k] = (row < M) ? A[(size_t)row * K + kc + k] : 0.f;
        }
        __syncthreads();
        if (active) {
            #pragma unroll 8
            for (int k = 0; k < KC; k++) {
                float4 w = *(const float4*)&Wsm[k * NP + tx * 4];
                float a0 = As[(ty * 4 + 0) * KP + k];
                float a1 = As[(ty * 4 + 1) * KP + k];
                float a2 = As[(ty * 4 + 2) * KP + k];
                float a3 = As[(ty * 4 + 3) * KP + k];
                acc[0][0] += a0 * w.x; acc[0][1] += a0 * w.y; acc[0][2] += a0 * w.z; acc[0][3] += a0 * w.w;
                acc[1][0] += a1 * w.x; acc[1][1] += a1 * w.y; acc[1][2] += a1 * w.z; acc[1][3] += a1 * w.w;
                acc[2][0] += a2 * w.x; acc[2][1] += a2 * w.y; acc[2][2] += a2 * w.z; acc[2][3] += a2 * w.w;
                acc[3][0] += a3 * w.x; acc[3][1] += a3 * w.y; acc[3][2] += a3 * w.z; acc[3][3] += a3 * w.w;
            }
        }
        __syncthreads();
    }

    if (MODE == 0) {
        float bx = __ldg(bias + tx * 4 + 0), by = __ldg(bias + tx * 4 + 1);
        float bz = __ldg(bias + tx * 4 + 2), bw = __ldg(bias + tx * 4 + 3);
        #pragma unroll
        for (int i = 0; i < 4; i++) {
            int row = row0 + ty * 4 + i;
            if (row < M) {
                float4 r4;
                r4.x = fmaxf(acc[i][0] + bx, 0.f);
                r4.y = fmaxf(acc[i][1] + by, 0.f);
                r4.z = fmaxf(acc[i][2] + bz, 0.f);
                r4.w = fmaxf(acc[i][3] + bw, 0.f);
                *(float4*)&g_X [(size_t)row * NHID_ + tx * 4] = r4;
                *(float4*)&g_X0[(size_t)row * NHID_ + tx * 4] = r4;
            }
        }
    } else if (MODE == 1) {
        #pragma unroll
        for (int i = 0; i < 4; i++) {
            int r = ty * 4 + i;
            int row = row0 + r;
            if (row < M) {
                float4 r4;
                r4.x = fmaxf(c0 * As[r * KP + tx * 4 + 0] + c1 * acc[i][0], 0.f);
                r4.y = fmaxf(c0 * As[r * KP + tx * 4 + 1] + c1 * acc[i][1], 0.f);
                r4.z = fmaxf(c0 * As[r * KP + tx * 4 + 2] + c1 * acc[i][2], 0.f);
                r4.w = fmaxf(c0 * As[r * KP + tx * 4 + 3] + c1 * acc[i][3], 0.f);
                *(float4*)&g_X[(size_t)row * NHID_ + tx * 4] = r4;
            }
        }
    } else {  // MODE 2: logits + fused log_softmax
        if (active) {
            #pragma unroll
            for (int i = 0; i < 4; i++) {
                int r = ty * 4 + i;
                #pragma unroll
                for (int j = 0; j < 4; j++)
                    Ls[r * NCOL + tx * 4 + j] = acc[i][j] + __ldg(bias + tx * 4 + j);
            }
        }
        __syncthreads();
        if (tid < 64) {
            int row = row0 + tid;
            if (row < M) {
                float mx = -1e30f;
                #pragma unroll
                for (int c = 0; c < NCOL; c++) mx = fmaxf(mx, Ls[tid * NCOL + c]);
                float s = 0.f;
                #pragma unroll
                for (int c = 0; c < NCOL; c++) s += __expf(Ls[tid * NCOL + c] - mx);
                float lse = mx + __logf(s);
                #pragma unroll
                for (int c = 0; c < NCOL; c++)
                    outext[(size_t)row * NCOL + c] = Ls[tid * NCOL + c] - lse;
            }
        }
    }
}

// ---------------- launch ----------------
extern "C" void kernel_launch(void* const* d_in, const int* in_sizes, int n_in,
                              void* d_out, int out_size)
{
    const float* x    = (const float*)d_in[0];
    const float* degE = (const float*)d_in[1];
    const float* degV = (const float*)d_in[2];
    const float* W0   = (const float*)d_in[3];
    const float* b0   = (const float*)d_in[4];
    const float* Ws   = (const float*)d_in[5];
    const float* Wout = (const float*)d_in[6];
    const float* bout = (const float*)d_in[7];
    const int* vertex = (const int*)d_in[8];
    const int* edges  = (const int*)d_in[9];
    float* out = (float*)d_out;

    (void)in_sizes; (void)n_in; (void)out_size;

    const int GB = (N_V + 63) / 64;
    const int Q4 = NNZ_ / 4;

    // CSR/CSC build (bump allocation, no serial scans; int4 MLP on atomics)
    zero_cnt_k<<<(N_V + 255) / 256, 256>>>();
    hist_k<<<(Q4 + 255) / 256, 256>>>((const int4*)vertex, (const int4*)edges);
    alloc_k<<<(NE_ + N_V + 255) / 256, 256>>>(degE);
    build_adj_k<<<(Q4 + 255) / 256, 256>>>((const int4*)vertex, (const int4*)edges);

    // X = relu(x @ W0 + b0); X0 = X
    gemm_k<128, 64, 0><<<GB, 256>>>(x, W0, b0, nullptr, 0.f, 0.f);

    for (int i = 0; i < NLAYER_; i++) {
        float beta = logf(0.5f / (float)(i + 1) + 1.0f);
        agg_ve_k<<<(NE_ + 7) / 8, 256>>>();
        agg_ev_k<<<(N_V + 7) / 8, 256>>>(degV);
        gemm_k<64, 64, 1><<<GB, 256>>>(nullptr, Ws + (size_t)i * NHID_ * NHID_,
                                       nullptr, nullptr, 1.0f - beta, beta);
    }

    // log_softmax(X @ Wout + bout)
    gemm_k<64, 40, 2><<<GB, 256>>>(nullptr, Wout, bout, out, 0.f, 0.f);
}